// round 11
// baseline (speedup 1.0000x reference)
#include <cuda_runtime.h>
#include <cuda_fp16.h>
#include <cstdint>

#define TT   8
#define NN   20000
#define EE   640000
#define HID  32
#define CAP  96          // padded slots per (t,node); slot 0 = self-loop
#define L2BLK 2500       // blocks per layer role (8 warps/block * 2500 = 20000 nodes)
#define SCB  625         // scatter blocks per timestep (256 thr * 4 edges * 625 = 640000)

// ---------------- static device scratch ----------------
__device__ int    g_cursor[TT * NN];
__device__ int    g_srclist[(size_t)TT * NN * CAP];
__device__ float  g_h2[2][NN * HID];    // double buffer (layer1 t+1 overlaps layer2 t)
__device__ float  g_as2[2][NN];
__device__ float  g_ad2[2][NN];
__device__ float  g_h[NN * HID];        // GRU hidden state
__device__ float  g_A1[4];              // As1[0..1], Ad1[0..1]
__device__ __half g_WihH[96 * 32];      // fp16 GRU weights (precomputed)
__device__ __half g_WhhH[96 * 32];
__device__ float4 g_W2T[32 * 16];       // W2T[c][k4] (precomputed transpose)

// ---------------- shared-memory layouts ----------------
struct L1S {
    float  W1[64], B1[64];
    float4 W2T[32][17];      // pitch 17 -> conflict-free
    float  As2[32], Ad2[32];
    float  z1[8][64];        // per-warp staging of z1 vector
};
struct L2S {
    __half Wih[96][40];      // pitch 40 halfs = 80B -> conflict-free LDS.128
    __half Whh[96][40];
    float  bih[96], bhh[96], b2[32], Wo[32];
    float  zz[8][32], hh[8][32], red[8][32];
};

__device__ __forceinline__ float dot8h(uint4 w, float4 a, float4 b) {
    float2 p0 = __half22float2(*(__half2*)&w.x);
    float2 p1 = __half22float2(*(__half2*)&w.y);
    float2 p2 = __half22float2(*(__half2*)&w.z);
    float2 p3 = __half22float2(*(__half2*)&w.w);
    return p0.x * a.x + p0.y * a.y + p1.x * a.z + p1.y * a.w
         + p2.x * b.x + p2.y * b.y + p3.x * b.z + p3.y * b.w;
}

// ---------------- setup: state init + weight precompute ----------------
__global__ void k_setup(const float* __restrict__ W1,
                        const float* __restrict__ as1,
                        const float* __restrict__ ad1,
                        const float* __restrict__ W2,
                        const float* __restrict__ Wih,
                        const float* __restrict__ Whh) {
    int i = blockIdx.x * blockDim.x + threadIdx.x;
    int stride = gridDim.x * blockDim.x;
    for (int j = i; j < NN * HID; j += stride) g_h[j] = 0.0f;
    for (int j = i; j < TT * NN; j += stride) {
        g_cursor[j] = 1;
        g_srclist[(size_t)j * CAP] = j % NN;   // self-loop in slot 0
    }
    for (int j = i; j < 96 * 32; j += stride) {
        g_WihH[j] = __float2half(Wih[j]);
        g_WhhH[j] = __float2half(Whh[j]);
    }
    for (int j = i; j < 512; j += stride) {
        int c = j >> 4, k4 = j & 15;
        g_W2T[j] = make_float4(W2[(4 * k4 + 0) * 32 + c], W2[(4 * k4 + 1) * 32 + c],
                               W2[(4 * k4 + 2) * 32 + c], W2[(4 * k4 + 3) * 32 + c]);
    }
    if (blockIdx.x == 0 && threadIdx.x < 4) {
        int h = threadIdx.x & 1;
        const float* a = (threadIdx.x >= 2) ? ad1 : as1;
        float s = 0.0f;
        for (int c = 0; c < HID; c++) s += W1[h * HID + c] * a[h * HID + c];
        g_A1[threadIdx.x] = s;
    }
}

// ---------------- scatter body: 4 edges per thread (int4 loads, 4 atomic chains) ----------------
__device__ __forceinline__ void scatter_body(const int* __restrict__ ei, int t, int sbid) {
    int i = (sbid * 256 + threadIdx.x) * 4;
    const size_t tb = (size_t)t * 2 * EE;
    int4 src = *(const int4*)&ei[tb + i];
    int4 dst = *(const int4*)&ei[tb + EE + i];
    int cb = t * NN;
    int p0 = atomicAdd(&g_cursor[cb + dst.x], 1);
    int p1 = atomicAdd(&g_cursor[cb + dst.y], 1);
    int p2 = atomicAdd(&g_cursor[cb + dst.z], 1);
    int p3 = atomicAdd(&g_cursor[cb + dst.w], 1);
    g_srclist[((size_t)cb + dst.x) * CAP + p0] = src.x;
    g_srclist[((size_t)cb + dst.y) * CAP + p1] = src.y;
    g_srclist[((size_t)cb + dst.z) * CAP + p2] = src.z;
    g_srclist[((size_t)cb + dst.w) * CAP + p3] = src.w;
}

// ---------------- layer 1 body ----------------
__device__ __forceinline__ void layer1_body(
        L1S* s, int bid,
        const float* __restrict__ xt,
        const float* __restrict__ W1, const float* __restrict__ b1,
        const float* __restrict__ as2w, const float* __restrict__ ad2w,
        int t) {
    int tid = threadIdx.x;
    for (int j = tid; j < 64; j += 256) { s->W1[j] = W1[j]; s->B1[j] = b1[j]; }
    for (int j = tid; j < 512; j += 256) {
        int c = j >> 4, k4 = j & 15;
        s->W2T[c][k4] = g_W2T[j];           // contiguous float4 gmem reads
    }
    for (int j = tid; j < 32; j += 256) { s->As2[j] = as2w[j]; s->Ad2[j] = ad2w[j]; }
    __syncthreads();

    int warp = tid >> 5, lane = tid & 31;
    int n = bid * 8 + warp;

    float As10 = g_A1[0], As11 = g_A1[1], Ad10 = g_A1[2], Ad11 = g_A1[3];
    float xd = xt[n];
    int deg = g_cursor[t * NN + n];
    const int* slp = g_srclist + ((size_t)t * NN + n) * CAP;

    float den0 = 0.f, den1 = 0.f, num0 = 0.f, num1 = 0.f;
    int e = lane;
    bool v = e < deg;
    int sidx = v ? slp[e] : 0;
    while (v) {
        int e2 = e + 32;
        bool v2 = e2 < deg;
        int s2 = v2 ? slp[e2] : 0;
        float xs = __ldg(&xt[sidx]);
        float r0 = xs * As10 + xd * Ad10; r0 = (r0 > 0.f) ? r0 : 0.2f * r0;
        float w0 = __expf(r0); den0 += w0; num0 += w0 * xs;
        float r1 = xs * As11 + xd * Ad11; r1 = (r1 > 0.f) ? r1 : 0.2f * r1;
        float w1 = __expf(r1); den1 += w1; num1 += w1 * xs;
        e = e2; v = v2; sidx = s2;
    }
#pragma unroll
    for (int o = 16; o; o >>= 1) {
        den0 += __shfl_xor_sync(0xffffffffu, den0, o);
        num0 += __shfl_xor_sync(0xffffffffu, num0, o);
        den1 += __shfl_xor_sync(0xffffffffu, den1, o);
        num1 += __shfl_xor_sync(0xffffffffu, num1, o);
    }
    float S0 = num0 / (den0 + 1e-16f);
    float S1 = num1 / (den1 + 1e-16f);

    float v0 = S0 * s->W1[lane] + s->B1[lane];
    float z1a = (v0 > 0.f) ? v0 : (__expf(v0) - 1.0f);
    float v1 = S1 * s->W1[32 + lane] + s->B1[32 + lane];
    float z1b = (v1 > 0.f) ? v1 : (__expf(v1) - 1.0f);

    s->z1[warp][lane] = z1a;
    s->z1[warp][32 + lane] = z1b;
    __syncwarp();

    float a = 0.f;
#pragma unroll
    for (int k4 = 0; k4 < 16; k4++) {
        float4 z4 = *(const float4*)&s->z1[warp][k4 * 4];   // broadcast
        float4 w4 = s->W2T[lane][k4];
        a += z4.x * w4.x + z4.y * w4.y + z4.z * w4.z + z4.w * w4.w;
    }
    int buf = t & 1;
    g_h2[buf][(size_t)n * HID + lane] = a;

    float p = a * s->As2[lane];
    float q = a * s->Ad2[lane];
#pragma unroll
    for (int o = 16; o; o >>= 1) {
        p += __shfl_xor_sync(0xffffffffu, p, o);
        q += __shfl_xor_sync(0xffffffffu, q, o);
    }
    if (lane == 0) { g_as2[buf][n] = p; g_ad2[buf][n] = q; }
}

// ---------------- layer 2 body: depth-2 pipelined gather + in-warp fp16-weight GRU ----------------
__device__ __forceinline__ void layer2_body(
        L2S* s, int bid,
        const float* __restrict__ b2,
        const float* __restrict__ bih, const float* __restrict__ bhh,
        const float* __restrict__ Wout, const float* __restrict__ bout,
        float* __restrict__ out, int t, int last) {
    int tid = threadIdx.x;
    for (int j = tid; j < 96 * 4; j += 256) {           // 4 uint4 per row
        int r = j >> 2, q = j & 3;
        *(uint4*)&s->Wih[r][q * 8] = ((const uint4*)g_WihH)[j];
        *(uint4*)&s->Whh[r][q * 8] = ((const uint4*)g_WhhH)[j];
    }
    for (int j = tid; j < 96; j += 256) { s->bih[j] = bih[j]; s->bhh[j] = bhh[j]; }
    for (int j = tid; j < 32; j += 256) { s->b2[j] = b2[j]; s->Wo[j] = Wout[j]; }
    __syncthreads();

    int warp = tid >> 5, lane = tid & 31;
    int glane = lane >> 3;          // edge group 0..3
    int clane = lane & 7;           // channel quarter
    int n = bid * 8 + warp;

    int buf = t & 1;
    const float* as2p = g_as2[buf];
    const float* h2p  = g_h2[buf];
    float ad2v = g_ad2[buf][n];
    int deg = g_cursor[t * NN + n];
    const int* slp = g_srclist + ((size_t)t * NN + n) * CAP;

    float hv = g_h[(size_t)n * HID + lane];   // hoisted: overlaps whole gather loop

    float4 acc = make_float4(0.f, 0.f, 0.f, 0.f);
    float den = 0.f;

    // depth-2 pipeline: two (as2, h2) pairs in flight per group
    int e0 = glane;
    bool u0 = e0 < deg;
    int s0 = u0 ? slp[e0] : 0;
    int e1 = e0 + 4;
    bool u1 = e1 < deg;
    int s1 = u1 ? slp[e1] : 0;
    float a0 = __ldg(&as2p[s0]);
    float4 h0 = *(const float4*)&h2p[(size_t)s0 * HID + (clane << 2)];
    float a1 = __ldg(&as2p[s1]);
    float4 h1 = *(const float4*)&h2p[(size_t)s1 * HID + (clane << 2)];
    int e2 = e1 + 4;
    bool u2 = e2 < deg;
    int s2 = u2 ? slp[e2] : 0;
    while (u0) {
        // issue stage-2 data loads + stage-3 index
        float a2 = __ldg(&as2p[s2]);
        float4 h2v = *(const float4*)&h2p[(size_t)s2 * HID + (clane << 2)];
        int e3 = e2 + 4;
        bool u3 = e3 < deg;
        int s3 = u3 ? slp[e3] : 0;
        // consume stage 0
        float r = a0 + ad2v; r = (r > 0.f) ? r : 0.2f * r;
        float w = __expf(r);
        den += w;
        acc.x += w * h0.x; acc.y += w * h0.y; acc.z += w * h0.z; acc.w += w * h0.w;
        // rotate
        a0 = a1; h0 = h1; u0 = u1;
        a1 = a2; h1 = h2v; u1 = u2;
        s2 = s3; u2 = u3; e2 = e3;
    }

#pragma unroll
    for (int o = 8; o <= 16; o <<= 1) {
        acc.x += __shfl_xor_sync(0xffffffffu, acc.x, o);
        acc.y += __shfl_xor_sync(0xffffffffu, acc.y, o);
        acc.z += __shfl_xor_sync(0xffffffffu, acc.z, o);
        acc.w += __shfl_xor_sync(0xffffffffu, acc.w, o);
        den   += __shfl_xor_sync(0xffffffffu, den, o);
    }
    if (glane == 0) *(float4*)&s->red[warp][clane << 2] = acc;
    __syncwarp();
    float o = s->red[warp][lane] / (den + 1e-16f) + s->b2[lane];
    float z2 = (o > 0.f) ? o : (__expf(o) - 1.0f);

    s->zz[warp][lane] = z2;
    s->hh[warp][lane] = hv;
    __syncwarp();

    float ri = 0.f, zi = 0.f, ni = 0.f, rh = 0.f, zh = 0.f, nh = 0.f;
#pragma unroll
    for (int k8 = 0; k8 < 4; k8++) {
        float4 zA = *(const float4*)&s->zz[warp][k8 * 8];       // broadcast
        float4 zB = *(const float4*)&s->zz[warp][k8 * 8 + 4];
        float4 hA = *(const float4*)&s->hh[warp][k8 * 8];
        float4 hB = *(const float4*)&s->hh[warp][k8 * 8 + 4];
        uint4 wr = *(const uint4*)&s->Wih[lane][k8 * 8];
        uint4 wz = *(const uint4*)&s->Wih[32 + lane][k8 * 8];
        uint4 wn = *(const uint4*)&s->Wih[64 + lane][k8 * 8];
        uint4 ur = *(const uint4*)&s->Whh[lane][k8 * 8];
        uint4 uz = *(const uint4*)&s->Whh[32 + lane][k8 * 8];
        uint4 un = *(const uint4*)&s->Whh[64 + lane][k8 * 8];
        ri += dot8h(wr, zA, zB);
        zi += dot8h(wz, zA, zB);
        ni += dot8h(wn, zA, zB);
        rh += dot8h(ur, hA, hB);
        zh += dot8h(uz, hA, hB);
        nh += dot8h(un, hA, hB);
    }
    float r = 1.0f / (1.0f + __expf(-(ri + s->bih[lane] + rh + s->bhh[lane])));
    float z = 1.0f / (1.0f + __expf(-(zi + s->bih[32 + lane] + zh + s->bhh[32 + lane])));
    float ng = tanhf(ni + s->bih[64 + lane] + r * (nh + s->bhh[64 + lane]));
    float hnew = (1.0f - z) * ng + z * hv;
    g_h[(size_t)n * HID + lane] = hnew;

    if (last) {
        float vv = hnew * s->Wo[lane];
#pragma unroll
        for (int o2 = 16; o2; o2 >>= 1) vv += __shfl_xor_sync(0xffffffffu, vv, o2);
        if (lane == 0) out[n] = vv + bout[0];
    }
}

// ---------------- kernels ----------------
__global__ void __launch_bounds__(256) k_scatter0(const int* __restrict__ ei) {
    scatter_body(ei, 0, blockIdx.x);
}

// blocks [0, 7*SCB): scatter t=1..7.  blocks [7*SCB, 7*SCB+L2BLK): layer1 at t=0.
__global__ void __launch_bounds__(256) k_scatter_l1(
        const int* __restrict__ ei,
        const float* xt, const float* W1, const float* b1,
        const float* as2w, const float* ad2w) {
    int bid = blockIdx.x;
    if (bid < 7 * SCB) {
        scatter_body(ei, 1 + bid / SCB, bid % SCB);
    } else {
        __shared__ L1S sm;
        layer1_body(&sm, bid - 7 * SCB, xt, W1, b1, as2w, ad2w, 0);
    }
}

// blocks [0, L2BLK): layer2 at t.  blocks [L2BLK, 2*L2BLK): layer1 at t+1.
__global__ void __launch_bounds__(256) k_fused(
        const float* xnext,
        const float* W1, const float* b1,
        const float* as2w, const float* ad2w,
        const float* b2,
        const float* bih, const float* bhh,
        const float* Wout, const float* bout,
        float* out, int t, int last) {
    __shared__ union { L1S l1; L2S l2; } sm;
    if ((int)blockIdx.x < L2BLK) {
        layer2_body(&sm.l2, blockIdx.x, b2, bih, bhh, Wout, bout, out, t, last);
    } else {
        layer1_body(&sm.l1, blockIdx.x - L2BLK, xnext, W1, b1, as2w, ad2w, t + 1);
    }
}

// ---------------- launcher ----------------
extern "C" void kernel_launch(void* const* d_in, const int* in_sizes, int n_in,
                              void* d_out, int out_size) {
    const float* x    = (const float*)d_in[0];
    const int*   ei   = (const int*)  d_in[1];
    const float* W1   = (const float*)d_in[2];
    const float* as1  = (const float*)d_in[3];
    const float* ad1  = (const float*)d_in[4];
    const float* b1   = (const float*)d_in[5];
    const float* W2   = (const float*)d_in[6];
    const float* as2  = (const float*)d_in[7];
    const float* ad2  = (const float*)d_in[8];
    const float* b2   = (const float*)d_in[9];
    const float* Wih  = (const float*)d_in[10];
    const float* Whh  = (const float*)d_in[11];
    const float* bih  = (const float*)d_in[12];
    const float* bhh  = (const float*)d_in[13];
    const float* Wout = (const float*)d_in[14];
    const float* bout = (const float*)d_in[15];
    float* out = (float*)d_out;

    k_setup<<<160, 256>>>(W1, as1, ad1, W2, Wih, Whh);
    k_scatter0<<<SCB, 256>>>(ei);
    k_scatter_l1<<<7 * SCB + L2BLK, 256>>>(ei, x, W1, b1, as2, ad2);
    for (int t = 0; t < TT - 1; t++) {
        const float* xnext = x + (size_t)(t + 1) * NN;
        k_fused<<<2 * L2BLK, 256>>>(xnext, W1, b1, as2, ad2,
                                    b2, bih, bhh, Wout, bout, out, t, 0);
    }
    k_fused<<<L2BLK, 256>>>(x, W1, b1, as2, ad2,
                            b2, bih, bhh, Wout, bout, out, TT - 1, 1);
}

// round 12
// speedup vs baseline: 1.1027x; 1.1027x over previous
#include <cuda_runtime.h>
#include <cuda_fp16.h>
#include <cstdint>

#define TT   8
#define NN   20000
#define EE   640000
#define HID  32
#define CAP  96          // padded slots per (t,node); slot 0 = self-loop
#define L2BLK 2500       // blocks per layer role (8 warps/block * 2500 = 20000 nodes)
#define SCB  625         // scatter blocks per timestep (256 thr * 4 edges * 625 = 640000)

// ---------------- static device scratch ----------------
__device__ int    g_cursor[TT * NN];
__device__ int    g_srclist[(size_t)TT * NN * CAP];
__device__ float  g_h2[2][NN * HID];    // double buffer (layer1 t+1 overlaps layer2 t)
__device__ float  g_as2[2][NN];
__device__ float  g_ad2[2][NN];
__device__ float  g_h[NN * HID];        // GRU hidden state
__device__ float  g_A1[4];              // As1[0..1], Ad1[0..1]
__device__ __half g_WihH[96 * 32];      // fp16 GRU weights (precomputed)
__device__ __half g_WhhH[96 * 32];
__device__ float4 g_W2T[32 * 16];       // W2T[c][k4] (precomputed transpose)

// ---------------- shared-memory layouts ----------------
struct L1S {
    float  W1[64], B1[64];
    float4 W2T[32][17];      // pitch 17 -> conflict-free
    float  As2[32], Ad2[32];
    float  z1[8][64];        // per-warp staging of z1 vector
};
struct L2S {
    __half Wih[96][40];      // pitch 40 halfs = 80B -> conflict-free LDS.128
    __half Whh[96][40];
    float  bih[96], bhh[96], b2[32], Wo[32];
    float  zz[8][32], hh[8][32], red[8][32];
};

__device__ __forceinline__ float dot8h(uint4 w, float4 a, float4 b) {
    float2 p0 = __half22float2(*(__half2*)&w.x);
    float2 p1 = __half22float2(*(__half2*)&w.y);
    float2 p2 = __half22float2(*(__half2*)&w.z);
    float2 p3 = __half22float2(*(__half2*)&w.w);
    return p0.x * a.x + p0.y * a.y + p1.x * a.z + p1.y * a.w
         + p2.x * b.x + p2.y * b.y + p3.x * b.z + p3.y * b.w;
}

// ---------------- setup: state init + weight precompute ----------------
__global__ void k_setup(const float* __restrict__ W1,
                        const float* __restrict__ as1,
                        const float* __restrict__ ad1,
                        const float* __restrict__ W2,
                        const float* __restrict__ Wih,
                        const float* __restrict__ Whh) {
    int i = blockIdx.x * blockDim.x + threadIdx.x;
    int stride = gridDim.x * blockDim.x;
    for (int j = i; j < NN * HID; j += stride) g_h[j] = 0.0f;
    for (int j = i; j < TT * NN; j += stride) {
        g_cursor[j] = 1;
        g_srclist[(size_t)j * CAP] = j % NN;   // self-loop in slot 0
    }
    for (int j = i; j < 96 * 32; j += stride) {
        g_WihH[j] = __float2half(Wih[j]);
        g_WhhH[j] = __float2half(Whh[j]);
    }
    for (int j = i; j < 512; j += stride) {
        int c = j >> 4, k4 = j & 15;
        g_W2T[j] = make_float4(W2[(4 * k4 + 0) * 32 + c], W2[(4 * k4 + 1) * 32 + c],
                               W2[(4 * k4 + 2) * 32 + c], W2[(4 * k4 + 3) * 32 + c]);
    }
    if (blockIdx.x == 0 && threadIdx.x < 4) {
        int h = threadIdx.x & 1;
        const float* a = (threadIdx.x >= 2) ? ad1 : as1;
        float s = 0.0f;
        for (int c = 0; c < HID; c++) s += W1[h * HID + c] * a[h * HID + c];
        g_A1[threadIdx.x] = s;
    }
}

// ---------------- scatter body: 4 edges per thread (int4 loads, 4 atomic chains) ----------------
__device__ __forceinline__ void scatter_body(const int* __restrict__ ei, int t, int sbid) {
    int i = (sbid * 256 + threadIdx.x) * 4;
    const size_t tb = (size_t)t * 2 * EE;
    int4 src = *(const int4*)&ei[tb + i];
    int4 dst = *(const int4*)&ei[tb + EE + i];
    int cb = t * NN;
    int p0 = atomicAdd(&g_cursor[cb + dst.x], 1);
    int p1 = atomicAdd(&g_cursor[cb + dst.y], 1);
    int p2 = atomicAdd(&g_cursor[cb + dst.z], 1);
    int p3 = atomicAdd(&g_cursor[cb + dst.w], 1);
    g_srclist[((size_t)cb + dst.x) * CAP + p0] = src.x;
    g_srclist[((size_t)cb + dst.y) * CAP + p1] = src.y;
    g_srclist[((size_t)cb + dst.z) * CAP + p2] = src.z;
    g_srclist[((size_t)cb + dst.w) * CAP + p3] = src.w;
}

// ---------------- layer 1 body ----------------
__device__ __forceinline__ void layer1_body(
        L1S* s, int bid,
        const float* __restrict__ xt,
        const float* __restrict__ W1, const float* __restrict__ b1,
        const float* __restrict__ as2w, const float* __restrict__ ad2w,
        int t) {
    int tid = threadIdx.x;
    for (int j = tid; j < 64; j += 256) { s->W1[j] = W1[j]; s->B1[j] = b1[j]; }
    for (int j = tid; j < 512; j += 256) {
        int c = j >> 4, k4 = j & 15;
        s->W2T[c][k4] = g_W2T[j];           // contiguous float4 gmem reads
    }
    for (int j = tid; j < 32; j += 256) { s->As2[j] = as2w[j]; s->Ad2[j] = ad2w[j]; }
    __syncthreads();

    int warp = tid >> 5, lane = tid & 31;
    int n = bid * 8 + warp;

    float As10 = g_A1[0], As11 = g_A1[1], Ad10 = g_A1[2], Ad11 = g_A1[3];
    float xd = xt[n];
    int deg = g_cursor[t * NN + n];
    const int* slp = g_srclist + ((size_t)t * NN + n) * CAP;

    float den0 = 0.f, den1 = 0.f, num0 = 0.f, num1 = 0.f;
    int e = lane;
    bool v = e < deg;
    int sidx = v ? slp[e] : 0;
    while (v) {
        int e2 = e + 32;
        bool v2 = e2 < deg;
        int s2 = v2 ? slp[e2] : 0;
        float xs = __ldg(&xt[sidx]);
        float r0 = xs * As10 + xd * Ad10; r0 = (r0 > 0.f) ? r0 : 0.2f * r0;
        float w0 = __expf(r0); den0 += w0; num0 += w0 * xs;
        float r1 = xs * As11 + xd * Ad11; r1 = (r1 > 0.f) ? r1 : 0.2f * r1;
        float w1 = __expf(r1); den1 += w1; num1 += w1 * xs;
        e = e2; v = v2; sidx = s2;
    }
#pragma unroll
    for (int o = 16; o; o >>= 1) {
        den0 += __shfl_xor_sync(0xffffffffu, den0, o);
        num0 += __shfl_xor_sync(0xffffffffu, num0, o);
        den1 += __shfl_xor_sync(0xffffffffu, den1, o);
        num1 += __shfl_xor_sync(0xffffffffu, num1, o);
    }
    float S0 = num0 / (den0 + 1e-16f);
    float S1 = num1 / (den1 + 1e-16f);

    float v0 = S0 * s->W1[lane] + s->B1[lane];
    float z1a = (v0 > 0.f) ? v0 : (__expf(v0) - 1.0f);
    float v1 = S1 * s->W1[32 + lane] + s->B1[32 + lane];
    float z1b = (v1 > 0.f) ? v1 : (__expf(v1) - 1.0f);

    s->z1[warp][lane] = z1a;
    s->z1[warp][32 + lane] = z1b;
    __syncwarp();

    float a = 0.f;
#pragma unroll
    for (int k4 = 0; k4 < 16; k4++) {
        float4 z4 = *(const float4*)&s->z1[warp][k4 * 4];   // broadcast
        float4 w4 = s->W2T[lane][k4];
        a += z4.x * w4.x + z4.y * w4.y + z4.z * w4.z + z4.w * w4.w;
    }
    int buf = t & 1;
    g_h2[buf][(size_t)n * HID + lane] = a;

    float p = a * s->As2[lane];
    float q = a * s->Ad2[lane];
#pragma unroll
    for (int o = 16; o; o >>= 1) {
        p += __shfl_xor_sync(0xffffffffu, p, o);
        q += __shfl_xor_sync(0xffffffffu, q, o);
    }
    if (lane == 0) { g_as2[buf][n] = p; g_ad2[buf][n] = q; }
}

// ---------------- layer 2 body: depth-1 pipelined gather + in-warp fp16-weight GRU (R10) ----------------
__device__ __forceinline__ void layer2_body(
        L2S* s, int bid,
        const float* __restrict__ b2,
        const float* __restrict__ bih, const float* __restrict__ bhh,
        const float* __restrict__ Wout, const float* __restrict__ bout,
        float* __restrict__ out, int t, int last) {
    int tid = threadIdx.x;
    for (int j = tid; j < 96 * 4; j += 256) {           // 4 uint4 per row
        int r = j >> 2, q = j & 3;
        *(uint4*)&s->Wih[r][q * 8] = ((const uint4*)g_WihH)[j];
        *(uint4*)&s->Whh[r][q * 8] = ((const uint4*)g_WhhH)[j];
    }
    for (int j = tid; j < 96; j += 256) { s->bih[j] = bih[j]; s->bhh[j] = bhh[j]; }
    for (int j = tid; j < 32; j += 256) { s->b2[j] = b2[j]; s->Wo[j] = Wout[j]; }
    __syncthreads();

    int warp = tid >> 5, lane = tid & 31;
    int glane = lane >> 3;          // edge group 0..3
    int clane = lane & 7;           // channel quarter
    int n = bid * 8 + warp;

    int buf = t & 1;
    const float* as2p = g_as2[buf];
    const float* h2p  = g_h2[buf];
    float ad2v = g_ad2[buf][n];
    int deg = g_cursor[t * NN + n];
    const int* slp = g_srclist + ((size_t)t * NN + n) * CAP;

    float4 acc = make_float4(0.f, 0.f, 0.f, 0.f);
    float den = 0.f;

    int e0 = glane;
    bool v0 = e0 < deg;
    int s0 = v0 ? slp[e0] : 0;
    float a0 = __ldg(&as2p[s0]);
    float4 h0 = *(const float4*)&h2p[(size_t)s0 * HID + (clane << 2)];
    int e1 = e0 + 4;
    bool v1 = e1 < deg;
    int s1 = v1 ? slp[e1] : 0;
    while (v0) {
        float a1 = __ldg(&as2p[s1]);
        float4 h1 = *(const float4*)&h2p[(size_t)s1 * HID + (clane << 2)];
        int e2 = e1 + 4;
        bool v2 = e2 < deg;
        int s2 = v2 ? slp[e2] : 0;
        float r = a0 + ad2v; r = (r > 0.f) ? r : 0.2f * r;
        float w = __expf(r);
        den += w;
        acc.x += w * h0.x; acc.y += w * h0.y; acc.z += w * h0.z; acc.w += w * h0.w;
        a0 = a1; h0 = h1; v0 = v1;
        s1 = s2; v1 = v2; e1 = e2;
    }

#pragma unroll
    for (int o = 8; o <= 16; o <<= 1) {
        acc.x += __shfl_xor_sync(0xffffffffu, acc.x, o);
        acc.y += __shfl_xor_sync(0xffffffffu, acc.y, o);
        acc.z += __shfl_xor_sync(0xffffffffu, acc.z, o);
        acc.w += __shfl_xor_sync(0xffffffffu, acc.w, o);
        den   += __shfl_xor_sync(0xffffffffu, den, o);
    }
    if (glane == 0) *(float4*)&s->red[warp][clane << 2] = acc;
    __syncwarp();
    float o = s->red[warp][lane] / (den + 1e-16f) + s->b2[lane];
    float z2 = (o > 0.f) ? o : (__expf(o) - 1.0f);
    float hv = g_h[(size_t)n * HID + lane];

    s->zz[warp][lane] = z2;
    s->hh[warp][lane] = hv;
    __syncwarp();

    float ri = 0.f, zi = 0.f, ni = 0.f, rh = 0.f, zh = 0.f, nh = 0.f;
#pragma unroll
    for (int k8 = 0; k8 < 4; k8++) {
        float4 zA = *(const float4*)&s->zz[warp][k8 * 8];       // broadcast
        float4 zB = *(const float4*)&s->zz[warp][k8 * 8 + 4];
        float4 hA = *(const float4*)&s->hh[warp][k8 * 8];
        float4 hB = *(const float4*)&s->hh[warp][k8 * 8 + 4];
        uint4 wr = *(const uint4*)&s->Wih[lane][k8 * 8];
        uint4 wz = *(const uint4*)&s->Wih[32 + lane][k8 * 8];
        uint4 wn = *(const uint4*)&s->Wih[64 + lane][k8 * 8];
        uint4 ur = *(const uint4*)&s->Whh[lane][k8 * 8];
        uint4 uz = *(const uint4*)&s->Whh[32 + lane][k8 * 8];
        uint4 un = *(const uint4*)&s->Whh[64 + lane][k8 * 8];
        ri += dot8h(wr, zA, zB);
        zi += dot8h(wz, zA, zB);
        ni += dot8h(wn, zA, zB);
        rh += dot8h(ur, hA, hB);
        zh += dot8h(uz, hA, hB);
        nh += dot8h(un, hA, hB);
    }
    float r = 1.0f / (1.0f + __expf(-(ri + s->bih[lane] + rh + s->bhh[lane])));
    float z = 1.0f / (1.0f + __expf(-(zi + s->bih[32 + lane] + zh + s->bhh[32 + lane])));
    float ng = tanhf(ni + s->bih[64 + lane] + r * (nh + s->bhh[64 + lane]));
    float hnew = (1.0f - z) * ng + z * hv;
    g_h[(size_t)n * HID + lane] = hnew;

    if (last) {
        float vv = hnew * s->Wo[lane];
#pragma unroll
        for (int o2 = 16; o2; o2 >>= 1) vv += __shfl_xor_sync(0xffffffffu, vv, o2);
        if (lane == 0) out[n] = vv + bout[0];
    }
}

// ---------------- kernels ----------------
__global__ void __launch_bounds__(256) k_scatter0(const int* __restrict__ ei) {
    scatter_body(ei, 0, blockIdx.x);
}

// blocks [0, 7*SCB): scatter t=1..7.  blocks [7*SCB, 7*SCB+L2BLK): layer1 at t=0.
__global__ void __launch_bounds__(256) k_scatter_l1(
        const int* __restrict__ ei,
        const float* xt, const float* W1, const float* b1,
        const float* as2w, const float* ad2w) {
    int bid = blockIdx.x;
    if (bid < 7 * SCB) {
        scatter_body(ei, 1 + bid / SCB, bid % SCB);
    } else {
        __shared__ L1S sm;
        layer1_body(&sm, bid - 7 * SCB, xt, W1, b1, as2w, ad2w, 0);
    }
}

// blocks [0, L2BLK): layer2 at t.  blocks [L2BLK, 2*L2BLK): layer1 at t+1.
__global__ void __launch_bounds__(256) k_fused(
        const float* xnext,
        const float* W1, const float* b1,
        const float* as2w, const float* ad2w,
        const float* b2,
        const float* bih, const float* bhh,
        const float* Wout, const float* bout,
        float* out, int t, int last) {
    __shared__ union { L1S l1; L2S l2; } sm;
    if ((int)blockIdx.x < L2BLK) {
        layer2_body(&sm.l2, blockIdx.x, b2, bih, bhh, Wout, bout, out, t, last);
    } else {
        layer1_body(&sm.l1, blockIdx.x - L2BLK, xnext, W1, b1, as2w, ad2w, t + 1);
    }
}

// ---------------- launcher ----------------
extern "C" void kernel_launch(void* const* d_in, const int* in_sizes, int n_in,
                              void* d_out, int out_size) {
    const float* x    = (const float*)d_in[0];
    const int*   ei   = (const int*)  d_in[1];
    const float* W1   = (const float*)d_in[2];
    const float* as1  = (const float*)d_in[3];
    const float* ad1  = (const float*)d_in[4];
    const float* b1   = (const float*)d_in[5];
    const float* W2   = (const float*)d_in[6];
    const float* as2  = (const float*)d_in[7];
    const float* ad2  = (const float*)d_in[8];
    const float* b2   = (const float*)d_in[9];
    const float* Wih  = (const float*)d_in[10];
    const float* Whh  = (const float*)d_in[11];
    const float* bih  = (const float*)d_in[12];
    const float* bhh  = (const float*)d_in[13];
    const float* Wout = (const float*)d_in[14];
    const float* bout = (const float*)d_in[15];
    float* out = (float*)d_out;

    k_setup<<<160, 256>>>(W1, as1, ad1, W2, Wih, Whh);
    k_scatter0<<<SCB, 256>>>(ei);
    k_scatter_l1<<<7 * SCB + L2BLK, 256>>>(ei, x, W1, b1, as2, ad2);
    for (int t = 0; t < TT - 1; t++) {
        const float* xnext = x + (size_t)(t + 1) * NN;
        k_fused<<<2 * L2BLK, 256>>>(xnext, W1, b1, as2, ad2,
                                    b2, bih, bhh, Wout, bout, out, t, 0);
    }
    k_fused<<<L2BLK, 256>>>(x, W1, b1, as2, ad2,
                            b2, bih, bhh, Wout, bout, out, TT - 1, 1);
}